// round 3
// baseline (speedup 1.0000x reference)
#include <cuda_runtime.h>

// Problem constants (from reference setup_inputs):
//   B = 262144, n_in = 128, n_middle = 512, n_extra = 2
// Inputs (metadata order): x [B,128] f32, w [B,1] f32, p [1,2] f32,
//                          W_in [512,130] f32, W_out [128,512] f32
// Output: [B,128] f32 = x + o  (o broadcast row)

#define N_IN      128
#define N_EXTRA   2
#define N_CAT     (N_IN + N_EXTRA)   // 130
#define N_MID     512
#define NBLK      1024               // stage-1 grid
#define T1        256                // stage-1 block

// Scratch (device globals — no allocation allowed).
// g_part layout: [col][block] so stage-2 per-column sums are contiguous.
__device__ float g_part[(N_IN + 1) * NBLK];  // cols 0..127 = v, col 128 = sum(w)
__device__ float g_o[N_IN];                  // broadcast row

// ---------------------------------------------------------------------------
// Stage 1: per-block weighted column sums.
// Block handles a contiguous chunk of rows. 256 threads = 8 row-groups x 32
// lanes; each lane owns 4 columns (float4). Coalesced 512B row reads.
// ---------------------------------------------------------------------------
__global__ void __launch_bounds__(T1)
stage1_reduce(const float* __restrict__ x, const float* __restrict__ w, int B)
{
    const int t   = threadIdx.x;
    const int c4  = t & 31;    // float4 column index (0..31)
    const int rg  = t >> 5;    // row group (0..7)

    const int rowsPerBlk = (B + gridDim.x - 1) / gridDim.x;
    const int r0   = blockIdx.x * rowsPerBlk;
    const int rEnd = min(r0 + rowsPerBlk, B);

    const float4* __restrict__ x4 = (const float4*)x;

    float4 acc = make_float4(0.f, 0.f, 0.f, 0.f);
    float  sw  = 0.f;

    #pragma unroll 4
    for (int r = r0 + rg; r < rEnd; r += 8) {
        float  ww = __ldg(&w[r]);
        float4 v  = x4[(long)r * 32 + c4];
        acc.x = fmaf(ww, v.x, acc.x);
        acc.y = fmaf(ww, v.y, acc.y);
        acc.z = fmaf(ww, v.z, acc.z);
        acc.w = fmaf(ww, v.w, acc.w);
        sw += ww;   // every lane in a row-group accumulates the same sw
    }

    __shared__ float s_v[8][N_IN];
    __shared__ float s_w[8];
    ((float4*)s_v[rg])[c4] = acc;
    if (c4 == 0) s_w[rg] = sw;
    __syncthreads();

    // first 129 threads: combine 8 row-groups, write transposed partials
    if (t < N_IN) {
        float vsum = 0.f;
        #pragma unroll
        for (int g = 0; g < 8; g++) vsum += s_v[g][t];
        g_part[t * NBLK + blockIdx.x] = vsum;
    } else if (t == N_IN) {
        float wsum = 0.f;
        #pragma unroll
        for (int g = 0; g < 8; g++) wsum += s_w[g];
        g_part[N_IN * NBLK + blockIdx.x] = wsum;
    }
}

// ---------------------------------------------------------------------------
// Stage 2 (single block, 512 threads): reduce partials, then the two tiny
// matvecs:  h = relu(W_in @ [v/s, p]),  o = W_out @ h.
// ---------------------------------------------------------------------------
__global__ void __launch_bounds__(512)
stage2_mid(const float* __restrict__ p,
           const float* __restrict__ W_in,
           const float* __restrict__ W_out)
{
    __shared__ float s_part4[N_IN + 1][4];
    __shared__ float s_sum[N_IN + 1];
    __shared__ float s_xbar[N_CAT];
    __shared__ float s_h[N_MID];

    const int t = threadIdx.x;

    // ---- reduce partials: 4 threads per column, 129 columns ----
    {
        const int part = t & 3;
        for (int col = t >> 2; col <= N_IN; col += 128) {
            const float* base = &g_part[col * NBLK + part * (NBLK / 4)];
            float s = 0.f;
            #pragma unroll 8
            for (int b = 0; b < NBLK / 4; b++) s += base[b];
            s_part4[col][part] = s;
        }
    }
    __syncthreads();
    if (t <= N_IN)
        s_sum[t] = s_part4[t][0] + s_part4[t][1] + s_part4[t][2] + s_part4[t][3];
    __syncthreads();

    // ---- xbar = [v/s, p0, p1] ----
    if (t < N_IN)       s_xbar[t] = s_sum[t] / s_sum[N_IN];
    else if (t < N_CAT) s_xbar[t] = p[t - N_IN];
    __syncthreads();

    // ---- h[m] = relu( dot(W_in[m,:], xbar) ), one thread per m ----
    {
        const float* __restrict__ row = W_in + (long)t * N_CAT;
        float acc = 0.f;
        #pragma unroll 10
        for (int k = 0; k < N_CAT; k++) acc = fmaf(row[k], s_xbar[k], acc);
        s_h[t] = fmaxf(acc, 0.f);
    }
    __syncthreads();

    // ---- o[i] = dot(W_out[i,:], h), first 128 threads ----
    if (t < N_IN) {
        const float* __restrict__ row = W_out + (long)t * N_MID;
        float acc = 0.f;
        #pragma unroll 8
        for (int m = 0; m < N_MID; m++) acc = fmaf(row[m], s_h[m], acc);
        g_o[t] = acc;
    }
}

// ---------------------------------------------------------------------------
// Stage 3: out = x + o  (float4 grid-stride, o staged in smem)
// ---------------------------------------------------------------------------
__global__ void __launch_bounds__(256)
stage3_add(const float* __restrict__ x, float* __restrict__ out, long n4)
{
    __shared__ float4 s_o[32];
    const int t = threadIdx.x;
    if (t < 32) s_o[t] = ((const float4*)g_o)[t];
    __syncthreads();

    const float4* __restrict__ x4 = (const float4*)x;
    float4* __restrict__ o4 = (float4*)out;

    const long stride = (long)gridDim.x * blockDim.x;
    for (long i = (long)blockIdx.x * blockDim.x + t; i < n4; i += stride) {
        float4 xv = x4[i];
        float4 ov = s_o[i & 31];        // 32 float4 per row
        xv.x += ov.x; xv.y += ov.y; xv.z += ov.z; xv.w += ov.w;
        o4[i] = xv;
    }
}

// ---------------------------------------------------------------------------
extern "C" void kernel_launch(void* const* d_in, const int* in_sizes, int n_in,
                              void* d_out, int out_size)
{
    const float* x     = (const float*)d_in[0];
    const float* w     = (const float*)d_in[1];
    const float* p     = (const float*)d_in[2];
    const float* W_in  = (const float*)d_in[3];
    const float* W_out = (const float*)d_in[4];
    float*       out   = (float*)d_out;

    const int  B  = in_sizes[0] / N_IN;       // 262144
    const long n4 = (long)B * (N_IN / 4);     // 8,388,608 float4

    stage1_reduce<<<NBLK, T1>>>(x, w, B);
    stage2_mid<<<1, 512>>>(p, W_in, W_out);

    int blocks3 = 4096;
    stage3_add<<<blocks3, 256>>>(x, out, n4);
}

// round 8
// speedup vs baseline: 1.3585x; 1.3585x over previous
#include <cuda_runtime.h>

// B = 262144, n_in = 128, n_middle = 512, n_extra = 2
// Inputs: x [B,128] f32, w [B,1] f32, p [1,2] f32,
//         W_in [512,130] f32, W_out [128,512] f32
// Output: [B,128] f32 = x + o (o is a broadcast row)
//
// Math: weighted_avg commutes with the linear maps, and the second
// weighted_avg of a constant row is identity, so:
//   v = sum_b w_b * x_b ; s = sum_b w_b ; xbar = [v/s, p]
//   h = relu(W_in @ xbar) ; o = W_out @ h ; out = x + o

#define N_IN   128
#define N_CAT  130
#define N_MID  512
#define NBLK   1024
#define PSTR   132              // padded partial row stride (floats); 132*4 % 8 == 0

// NOTE: every array cast to float2/float4 must be explicitly 16B-aligned —
// plain float arrays are only 4B-aligned (R3 failure: misaligned address).
__device__ __align__(16) float g_part[NBLK * PSTR];   // [block][col 0..127]
__device__ __align__(16) float g_wpart[NBLK];         // per-block sum(w)
__device__ __align__(16) float g_o[N_IN];             // broadcast row
__device__ int g_count = 0;                           // last-block ticket (self-resetting)

__device__ __forceinline__ void fma4(float4& a, float s, const float4& v) {
    a.x = fmaf(s, v.x, a.x);
    a.y = fmaf(s, v.y, a.y);
    a.z = fmaf(s, v.z, a.z);
    a.w = fmaf(s, v.w, a.w);
}

__device__ __forceinline__ float warp_sum(float v) {
    #pragma unroll
    for (int off = 16; off; off >>= 1)
        v += __shfl_down_sync(0xffffffffu, v, off);
    return v;
}

// ---------------------------------------------------------------------------
// K1: weighted column sums (all blocks) + last block reduces partials and
//     runs the two tiny matvecs.
// ---------------------------------------------------------------------------
__global__ void __launch_bounds__(256)
k1_reduce_mid(const float* __restrict__ x, const float* __restrict__ w,
              const float* __restrict__ p, const float* __restrict__ W_in,
              const float* __restrict__ W_out, int B)
{
    const int t    = threadIdx.x;
    const int c4   = t & 31;          // float4 column (0..31)
    const int rg   = t >> 5;          // warp id (0..7)
    const int rowsPerBlk = B / NBLK;  // 256
    const int r0   = blockIdx.x * rowsPerBlk;
    const int nG   = rowsPerBlk >> 5; // groups of 4 rows per warp (8)

    const float4* __restrict__ x4  = (const float4*)x;
    const float4* __restrict__ w4p = (const float4*)w;

    float4 acc = make_float4(0.f, 0.f, 0.f, 0.f);
    float  sw  = 0.f;

    #pragma unroll 2
    for (int g = 0; g < nG; g++) {
        const int rbase = r0 + rg * 4 + g * 32;      // multiple of 4
        const float4 wv = __ldg(&w4p[rbase >> 2]);
        const long base = (long)rbase * 32 + c4;
        float4 a0 = x4[base];
        float4 a1 = x4[base + 32];
        float4 a2 = x4[base + 64];
        float4 a3 = x4[base + 96];
        fma4(acc, wv.x, a0);
        fma4(acc, wv.y, a1);
        fma4(acc, wv.z, a2);
        fma4(acc, wv.w, a3);
        sw += (wv.x + wv.y) + (wv.z + wv.w);
    }

    __shared__ __align__(16) float s_v[8][N_IN];
    __shared__ float s_w[8];
    ((float4*)s_v[rg])[c4] = acc;
    if (c4 == 0) s_w[rg] = sw;
    __syncthreads();

    // coalesced partial write: 128 consecutive floats + wsum
    if (t < N_IN) {
        float vs = 0.f;
        #pragma unroll
        for (int g = 0; g < 8; g++) vs += s_v[g][t];
        g_part[blockIdx.x * PSTR + t] = vs;
    } else if (t == N_IN) {
        float ws = 0.f;
        #pragma unroll
        for (int g = 0; g < 8; g++) ws += s_w[g];
        g_wpart[blockIdx.x] = ws;
    }
    __threadfence();
    __syncthreads();

    __shared__ int s_last;
    if (t == 0) s_last = (atomicAdd(&g_count, 1) == NBLK - 1);
    __syncthreads();
    if (!s_last) return;

    // ================= last block: reduce + matvecs =================
    __threadfence();

    __shared__ __align__(16) float s_red[4][N_IN];
    __shared__ float s_wp[256];
    __shared__ float s_xbar[N_CAT];
    __shared__ float s_h[N_MID];
    __shared__ float s_stot;

    // partial reduce: 4 block-quarters x 64 float2 columns, coalesced.
    // offsets: base 16B-aligned, row stride 528B (mult of 8), col 8B -> legal.
    {
        const int part = t >> 6;           // 0..3
        const int c2   = t & 63;           // float2 column
        float2 s2 = make_float2(0.f, 0.f);
        const int b0 = part * (NBLK / 4);
        #pragma unroll 8
        for (int b = 0; b < NBLK / 4; b++) {
            float2 v = *(const float2*)&g_part[(b0 + b) * PSTR + 2 * c2];
            s2.x += v.x; s2.y += v.y;
        }
        ((float2*)s_red[part])[c2] = s2;
    }
    // wsum partials: coalesced
    {
        float s = g_wpart[t] + g_wpart[t + 256] + g_wpart[t + 512] + g_wpart[t + 768];
        s_wp[t] = s;
    }
    __syncthreads();

    if (t < 32) {
        float s = 0.f;
        #pragma unroll
        for (int k = 0; k < 8; k++) s += s_wp[t + 32 * k];
        s = warp_sum(s);
        if (t == 0) s_stot = s;
    }
    __syncthreads();

    if (t < N_IN)
        s_xbar[t] = (s_red[0][t] + s_red[1][t] + s_red[2][t] + s_red[3][t]) / s_stot;
    else if (t < N_CAT)
        s_xbar[t] = p[t - N_IN];
    __syncthreads();

    // h = relu(W_in @ xbar): warp per row, coalesced W_in reads
    {
        const int lane = t & 31, wid = t >> 5;
        for (int r = wid; r < N_MID; r += 8) {
            const float* __restrict__ row = W_in + (long)r * N_CAT;
            float acc2 = 0.f;
            #pragma unroll
            for (int k = lane; k < N_CAT; k += 32)
                acc2 = fmaf(row[k], s_xbar[k], acc2);
            acc2 = warp_sum(acc2);
            if (lane == 0) s_h[r] = fmaxf(acc2, 0.f);
        }
    }
    __syncthreads();

    // o = W_out @ h: warp per row
    {
        const int lane = t & 31, wid = t >> 5;
        for (int r = wid; r < N_IN; r += 8) {
            const float* __restrict__ row = W_out + (long)r * N_MID;
            float acc2 = 0.f;
            #pragma unroll
            for (int k = lane; k < N_MID; k += 32)
                acc2 = fmaf(row[k], s_h[k], acc2);
            acc2 = warp_sum(acc2);
            if (lane == 0) g_o[r] = acc2;
        }
    }

    if (t == 0) g_count = 0;   // reset for next graph replay
}

// ---------------------------------------------------------------------------
// K2: out = x + o. Streaming hints: x won't be read again, out never read —
// evict-first on both so out-writes don't purge x that's still L2-resident.
// ---------------------------------------------------------------------------
__global__ void __launch_bounds__(256)
k2_add(const float* __restrict__ x, float* __restrict__ out, long n4)
{
    __shared__ __align__(16) float4 s_o[32];
    const int t = threadIdx.x;
    if (t < 32) {
        // g_o is 16B-aligned (declared __align__(16)) -> float4 load legal
        s_o[t] = ((const float4*)g_o)[t];
    }
    __syncthreads();

    const float4* __restrict__ x4 = (const float4*)x;
    float4* __restrict__ o4 = (float4*)out;

    const long stride = (long)gridDim.x * blockDim.x;
    for (long i = (long)blockIdx.x * blockDim.x + t; i < n4; i += stride) {
        float4 xv = __ldcs(&x4[i]);
        float4 ov = s_o[i & 31];
        xv.x += ov.x; xv.y += ov.y; xv.z += ov.z; xv.w += ov.w;
        __stcs(&o4[i], xv);
    }
}

// ---------------------------------------------------------------------------
extern "C" void kernel_launch(void* const* d_in, const int* in_sizes, int n_in,
                              void* d_out, int out_size)
{
    const float* x     = (const float*)d_in[0];
    const float* w     = (const float*)d_in[1];
    const float* p     = (const float*)d_in[2];
    const float* W_in  = (const float*)d_in[3];
    const float* W_out = (const float*)d_in[4];
    float*       out   = (float*)d_out;

    const int  B  = in_sizes[0] / N_IN;
    const long n4 = (long)B * (N_IN / 4);

    k1_reduce_mid<<<NBLK, 256>>>(x, w, p, W_in, W_out, B);
    k2_add<<<4096, 256>>>(x, out, n4);
}

// round 9
// speedup vs baseline: 2.9290x; 2.1561x over previous
#include <cuda_runtime.h>

// B = 262144, n_in = 128, n_middle = 512, n_extra = 2
// Inputs: x [B,128] f32, w [B,1] f32, p [1,2] f32,
//         W_in [512,130] f32, W_out [128,512] f32
// Output: [B,128] f32 = x + o (o is a broadcast row)
//
// Math: weighted_avg commutes with the linear maps, and the second
// weighted_avg of a constant row is identity:
//   v = sum_b w_b * x_b ; s = sum_b w_b ; xbar = [v/s, p]
//   h = relu(W_in @ xbar) ; o = W_out @ h ; out = x + o

#define N_IN   128
#define N_CAT  130
#define N_MID  512
#define NBLK   1024
#define PSTR   132   // partial row stride (floats)

__device__ __align__(16) float g_part[NBLK * PSTR];   // [block][col 0..127]
__device__ __align__(16) float g_wpart[NBLK];         // per-block sum(w)
__device__ __align__(16) float g_o[N_IN];             // broadcast row

__device__ __forceinline__ void fma4(float4& a, float s, const float4& v) {
    a.x = fmaf(s, v.x, a.x);
    a.y = fmaf(s, v.y, a.y);
    a.z = fmaf(s, v.z, a.z);
    a.w = fmaf(s, v.w, a.w);
}

__device__ __forceinline__ float warp_sum(float v) {
    #pragma unroll
    for (int off = 16; off; off >>= 1)
        v += __shfl_down_sync(0xffffffffu, v, off);
    return v;
}

// ---------------------------------------------------------------------------
// K1: per-block weighted column sums ONLY (keeps regs ~32, occupancy high).
// ---------------------------------------------------------------------------
__global__ void __launch_bounds__(256)
k1_partial(const float* __restrict__ x, const float* __restrict__ w, int B)
{
    const int t  = threadIdx.x;
    const int c4 = t & 31;            // float4 column (0..31)
    const int rg = t >> 5;            // warp id (0..7)
    const int rowsPerBlk = B / NBLK;  // 256
    const int r0 = blockIdx.x * rowsPerBlk;
    const int nG = rowsPerBlk >> 5;   // 8 groups of 4 rows per warp

    const float4* __restrict__ x4  = (const float4*)x;
    const float4* __restrict__ w4p = (const float4*)w;

    float4 acc = make_float4(0.f, 0.f, 0.f, 0.f);
    float  sw  = 0.f;

    #pragma unroll 2
    for (int g = 0; g < nG; g++) {
        const int rbase = r0 + rg * 4 + g * 32;
        const float4 wv = __ldg(&w4p[rbase >> 2]);
        const long base = (long)rbase * 32 + c4;
        float4 a0 = x4[base];
        float4 a1 = x4[base + 32];
        float4 a2 = x4[base + 64];
        float4 a3 = x4[base + 96];
        fma4(acc, wv.x, a0);
        fma4(acc, wv.y, a1);
        fma4(acc, wv.z, a2);
        fma4(acc, wv.w, a3);
        sw += (wv.x + wv.y) + (wv.z + wv.w);
    }

    __shared__ __align__(16) float s_v[8][N_IN];
    __shared__ float s_w[8];
    ((float4*)s_v[rg])[c4] = acc;
    if (c4 == 0) s_w[rg] = sw;
    __syncthreads();

    if (t < N_IN) {
        float vs = 0.f;
        #pragma unroll
        for (int g = 0; g < 8; g++) vs += s_v[g][t];
        g_part[blockIdx.x * PSTR + t] = vs;      // coalesced 512B per block
    } else if (t == N_IN) {
        float ws = 0.f;
        #pragma unroll
        for (int g = 0; g < 8; g++) ws += s_w[g];
        g_wpart[blockIdx.x] = ws;
    }
}

// ---------------------------------------------------------------------------
// K1b: one block, 1024 threads (32 warps).
//   a) coalesced column reduce of g_part (8 block-groups x 128 cols, MLP 8)
//   b) xbar = [v/s, p]
//   c) h = relu(W_in @ xbar), 32 warps x 16 rows, coalesced + shfl reduce
//   d) o = W_out @ h, 32 warps x 4 rows
// ---------------------------------------------------------------------------
__global__ void __launch_bounds__(1024)
k1b_mid(const float* __restrict__ p, const float* __restrict__ W_in,
        const float* __restrict__ W_out)
{
    const int t    = threadIdx.x;
    const int lane = t & 31;
    const int wid  = t >> 5;          // 0..31

    __shared__ float s_red[8][N_IN];
    __shared__ float s_wp[32];
    __shared__ float s_xbar[N_CAT];
    __shared__ float s_h[N_MID];
    __shared__ float s_stot;

    // a) column partial reduce: group g handles blocks [g*128, g*128+128)
    {
        const int g   = t >> 7;       // 0..7
        const int col = t & 127;      // 0..127
        const int b0  = g * (NBLK / 8);
        float s = 0.f;
        #pragma unroll 8
        for (int b = 0; b < NBLK / 8; b++)
            s += g_part[(b0 + b) * PSTR + col];   // 32 lanes consecutive -> coalesced
        s_red[g][col] = s;
    }
    // wsum: one element per thread, then shfl + cross-warp combine
    {
        float s = warp_sum(g_wpart[t]);
        if (lane == 0) s_wp[wid] = s;
    }
    __syncthreads();

    if (wid == 0) {
        float s = warp_sum(s_wp[lane]);
        if (lane == 0) s_stot = s;
    }
    __syncthreads();

    if (t < N_IN) {
        float v = 0.f;
        #pragma unroll
        for (int g = 0; g < 8; g++) v += s_red[g][t];
        s_xbar[t] = v / s_stot;
    } else if (t < N_CAT) {
        s_xbar[t] = p[t - N_IN];
    }
    __syncthreads();

    // c) h = relu(W_in @ xbar): 512 rows / 32 warps = 16 rows per warp
    for (int r = wid; r < N_MID; r += 32) {
        const float* __restrict__ row = W_in + (long)r * N_CAT;
        float acc = 0.f;
        #pragma unroll
        for (int k = lane; k < N_CAT; k += 32)
            acc = fmaf(row[k], s_xbar[k], acc);
        acc = warp_sum(acc);
        if (lane == 0) s_h[r] = fmaxf(acc, 0.f);
    }
    __syncthreads();

    // d) o = W_out @ h: 128 rows / 32 warps = 4 rows per warp
    for (int r = wid; r < N_IN; r += 32) {
        const float* __restrict__ row = W_out + (long)r * N_MID;
        float acc = 0.f;
        #pragma unroll
        for (int k = lane; k < N_MID; k += 32)
            acc = fmaf(row[k], s_h[k], acc);
        acc = warp_sum(acc);
        if (lane == 0) g_o[r] = acc;
    }
}

// ---------------------------------------------------------------------------
// K2: out = x + o. Already at ~95% of the LTS cap — unchanged.
// ---------------------------------------------------------------------------
__global__ void __launch_bounds__(256)
k2_add(const float* __restrict__ x, float* __restrict__ out, long n4)
{
    __shared__ __align__(16) float4 s_o[32];
    const int t = threadIdx.x;
    if (t < 32) s_o[t] = ((const float4*)g_o)[t];
    __syncthreads();

    const float4* __restrict__ x4 = (const float4*)x;
    float4* __restrict__ o4 = (float4*)out;

    const long stride = (long)gridDim.x * blockDim.x;
    for (long i = (long)blockIdx.x * blockDim.x + t; i < n4; i += stride) {
        float4 xv = __ldcs(&x4[i]);
        float4 ov = s_o[i & 31];
        xv.x += ov.x; xv.y += ov.y; xv.z += ov.z; xv.w += ov.w;
        __stcs(&o4[i], xv);
    }
}

// ---------------------------------------------------------------------------
extern "C" void kernel_launch(void* const* d_in, const int* in_sizes, int n_in,
                              void* d_out, int out_size)
{
    const float* x     = (const float*)d_in[0];
    const float* w     = (const float*)d_in[1];
    const float* p     = (const float*)d_in[2];
    const float* W_in  = (const float*)d_in[3];
    const float* W_out = (const float*)d_in[4];
    float*       out   = (float*)d_out;

    const int  B  = in_sizes[0] / N_IN;
    const long n4 = (long)B * (N_IN / 4);

    k1_partial<<<NBLK, 256>>>(x, w, B);
    k1b_mid<<<1, 1024>>>(p, W_in, W_out);
    k2_add<<<4096, 256>>>(x, out, n4);
}

// round 10
// speedup vs baseline: 3.2202x; 1.0994x over previous
#include <cuda_runtime.h>

// B = 262144, n_in = 128, n_middle = 512, n_extra = 2
// Inputs: x [B,128] f32, w [B,1] f32, p [1,2] f32,
//         W_in [512,130] f32, W_out [128,512] f32
// Output: [B,128] f32 = x + o (o is a broadcast row)
//
// Math: weighted_avg commutes with the linear maps, and the second
// weighted_avg of a constant row is identity:
//   v = sum_b w_b * x_b ; s = sum_b w_b ; xbar = [v/s, p]
//   h = relu(W_in @ xbar) ; o = W_out @ h ; out = x + o

#define N_IN   128
#define N_CAT  130
#define N_MID  512
#define NBLK   1024
#define PSTR   132   // partial row stride (floats); 132*4=528 B, 16B-aligned rows

__device__ __align__(16) float g_part[NBLK * PSTR];   // [block][col 0..127]
__device__ __align__(16) float g_wpart[NBLK];         // per-block sum(w)
__device__ __align__(16) float g_o[N_IN];             // broadcast row
__device__ float g_scratch[128];                      // sink for W prefetch (never read)

__device__ __forceinline__ void fma4(float4& a, float s, const float4& v) {
    a.x = fmaf(s, v.x, a.x);
    a.y = fmaf(s, v.y, a.y);
    a.z = fmaf(s, v.z, a.z);
    a.w = fmaf(s, v.w, a.w);
}

__device__ __forceinline__ float warp_sum(float v) {
    #pragma unroll
    for (int off = 16; off; off >>= 1)
        v += __shfl_down_sync(0xffffffffu, v, off);
    return v;
}

// ---------------------------------------------------------------------------
// K1: per-block weighted column sums. First 128 blocks additionally stream
// the W matrices through L2 (__ldcg) so k1b's weight reads hit L2.
// ---------------------------------------------------------------------------
__global__ void __launch_bounds__(256)
k1_partial(const float* __restrict__ x, const float* __restrict__ w,
           const float* __restrict__ W_in, const float* __restrict__ W_out, int B)
{
    const int t  = threadIdx.x;
    const int c4 = t & 31;            // float4 column (0..31)
    const int rg = t >> 5;            // warp id (0..7)
    const int rowsPerBlk = B / NBLK;  // 256
    const int r0 = blockIdx.x * rowsPerBlk;
    const int nG = rowsPerBlk >> 5;   // 8 groups of 4 rows per warp

    // L2 warm for k1b: blocks 0..63 stream W_in, 64..127 stream W_out.
    if (blockIdx.x < 128) {
        const bool second = blockIdx.x >= 64;
        const float* __restrict__ src = second ? W_out : W_in;
        const int total = second ? (N_IN * N_MID) : (N_MID * N_CAT);
        const int slice = (total + 63) / 64;
        const int b     = second ? (int)blockIdx.x - 64 : (int)blockIdx.x;
        const int lo    = b * slice;
        const int hi    = min(lo + slice, total);
        float s = 0.f;
        for (int i = lo + t; i < hi; i += 256) s += __ldcg(&src[i]);
        if (t == 0) g_scratch[blockIdx.x] = s;   // keep loads live; never read
    }

    const float4* __restrict__ x4  = (const float4*)x;
    const float4* __restrict__ w4p = (const float4*)w;

    float4 acc = make_float4(0.f, 0.f, 0.f, 0.f);
    float  sw  = 0.f;

    #pragma unroll 2
    for (int g = 0; g < nG; g++) {
        const int rbase = r0 + rg * 4 + g * 32;
        const float4 wv = __ldg(&w4p[rbase >> 2]);
        const long base = (long)rbase * 32 + c4;
        float4 a0 = x4[base];
        float4 a1 = x4[base + 32];
        float4 a2 = x4[base + 64];
        float4 a3 = x4[base + 96];
        fma4(acc, wv.x, a0);
        fma4(acc, wv.y, a1);
        fma4(acc, wv.z, a2);
        fma4(acc, wv.w, a3);
        sw += (wv.x + wv.y) + (wv.z + wv.w);
    }

    __shared__ __align__(16) float s_v[8][N_IN];
    __shared__ float s_w[8];
    ((float4*)s_v[rg])[c4] = acc;
    if (c4 == 0) s_w[rg] = sw;
    __syncthreads();

    if (t < N_IN) {
        float vs = 0.f;
        #pragma unroll
        for (int g = 0; g < 8; g++) vs += s_v[g][t];
        g_part[blockIdx.x * PSTR + t] = vs;      // coalesced 512B per block
    } else if (t == N_IN) {
        float ws = 0.f;
        #pragma unroll
        for (int g = 0; g < 8; g++) ws += s_w[g];
        g_wpart[blockIdx.x] = ws;
    }
}

// ---------------------------------------------------------------------------
// K1b: one block, 1024 threads (32 warps).
//   a) float4 column reduce of g_part: 32 groups x 32 float4-cols,
//      chain depth 32 (was 128)
//   b) xbar = [v/s, p]
//   c) h = relu(W_in @ xbar), warp-per-row, rows unrolled for ILP
//   d) o = W_out @ h, warp-per-row
// ---------------------------------------------------------------------------
__global__ void __launch_bounds__(1024)
k1b_mid(const float* __restrict__ p, const float* __restrict__ W_in,
        const float* __restrict__ W_out)
{
    const int t    = threadIdx.x;
    const int lane = t & 31;
    const int wid  = t >> 5;          // 0..31

    // 129-float row stride: column reads (fixed col, varying group) hit
    // distinct banks (129 mod 32 == 1).
    __shared__ float s_red[32][129];
    __shared__ float s_wp[32];
    __shared__ float s_xbar[N_CAT];
    __shared__ float s_h[N_MID];
    __shared__ float s_stot;

    // a) group g sums blocks [g*32, g*32+32); each thread owns one float4 col
    {
        const int g  = t >> 5;        // 0..31 (== wid)
        const int c4 = t & 31;        // float4 column
        const int b0 = g * (NBLK / 32);
        float4 a = make_float4(0.f, 0.f, 0.f, 0.f);
        #pragma unroll 8
        for (int b = 0; b < NBLK / 32; b++) {
            // byte offset (528*(b0+b) + 16*c4) is 16B-aligned
            const float4 v = *(const float4*)&g_part[(b0 + b) * PSTR + 4 * c4];
            a.x += v.x; a.y += v.y; a.z += v.z; a.w += v.w;
        }
        s_red[g][4 * c4 + 0] = a.x;
        s_red[g][4 * c4 + 1] = a.y;
        s_red[g][4 * c4 + 2] = a.z;
        s_red[g][4 * c4 + 3] = a.w;
    }
    // wsum: 1024 elements, one per thread
    {
        float s = warp_sum(g_wpart[t]);
        if (lane == 0) s_wp[wid] = s;
    }
    __syncthreads();

    if (wid == 0) {
        float s = warp_sum(s_wp[lane]);
        if (lane == 0) s_stot = s;
    }
    __syncthreads();

    if (t < N_IN) {
        float v = 0.f;
        #pragma unroll
        for (int g = 0; g < 32; g++) v += s_red[g][t];   // conflict-free
        s_xbar[t] = v / s_stot;
    } else if (t < N_CAT) {
        s_xbar[t] = p[t - N_IN];
    }
    __syncthreads();

    // c) h = relu(W_in @ xbar): 512 rows / 32 warps; unroll rows for ILP
    #pragma unroll 4
    for (int r = wid; r < N_MID; r += 32) {
        const float* __restrict__ row = W_in + (long)r * N_CAT;
        float acc = 0.f;
        #pragma unroll
        for (int k = lane; k < N_CAT; k += 32)
            acc = fmaf(row[k], s_xbar[k], acc);
        acc = warp_sum(acc);
        if (lane == 0) s_h[r] = fmaxf(acc, 0.f);
    }
    __syncthreads();

    // d) o = W_out @ h: 128 rows / 32 warps
    #pragma unroll
    for (int r = wid; r < N_IN; r += 32) {
        const float* __restrict__ row = W_out + (long)r * N_MID;
        float acc = 0.f;
        #pragma unroll
        for (int k = lane; k < N_MID; k += 32)
            acc = fmaf(row[k], s_h[k], acc);
        acc = warp_sum(acc);
        if (lane == 0) g_o[r] = acc;
    }
}

// ---------------------------------------------------------------------------
// K2: out = x + o. Unroll for MLP; streaming hints keep L2 for x.
// ---------------------------------------------------------------------------
__global__ void __launch_bounds__(256)
k2_add(const float* __restrict__ x, float* __restrict__ out, long n4)
{
    __shared__ __align__(16) float4 s_o[32];
    const int t = threadIdx.x;
    if (t < 32) s_o[t] = ((const float4*)g_o)[t];
    __syncthreads();

    const float4* __restrict__ x4 = (const float4*)x;
    float4* __restrict__ o4 = (float4*)out;

    const long stride = (long)gridDim.x * blockDim.x;
    #pragma unroll 4
    for (long i = (long)blockIdx.x * blockDim.x + t; i < n4; i += stride) {
        float4 xv = __ldcs(&x4[i]);
        float4 ov = s_o[i & 31];
        xv.x += ov.x; xv.y += ov.y; xv.z += ov.z; xv.w += ov.w;
        __stcs(&o4[i], xv);
    }
}

// ---------------------------------------------------------------------------
extern "C" void kernel_launch(void* const* d_in, const int* in_sizes, int n_in,
                              void* d_out, int out_size)
{
    const float* x     = (const float*)d_in[0];
    const float* w     = (const float*)d_in[1];
    const float* p     = (const float*)d_in[2];
    const float* W_in  = (const float*)d_in[3];
    const float* W_out = (const float*)d_in[4];
    float*       out   = (float*)d_out;

    const int  B  = in_sizes[0] / N_IN;
    const long n4 = (long)B * (N_IN / 4);

    k1_partial<<<NBLK, 256>>>(x, w, W_in, W_out, B);
    k1b_mid<<<1, 1024>>>(p, W_in, W_out);
    k2_add<<<4096, 256>>>(x, out, n4);
}